// round 3
// baseline (speedup 1.0000x reference)
#include <cuda_runtime.h>

// Fused Allen-Cahn step, smem-tiled with front-batched loads for max MLP.
//   out = ALPHA*x - ALPHA*x^3 + BETA*(N + S + W + E - 4x), replication pad.
// Shape: (16, 1, 1024, 1024) fp32. 64MB in + 64MB out.

#define ALPHA 400.0f
#define BETA  10000.0f

static constexpr int W = 1024;
static constexpr int H = 1024;
static constexpr int NIMG = 16;
static constexpr int VEC = 4;            // float4
static constexpr int TPB = W / VEC;      // 256 threads = one full row of float4
static constexpr int RPT = 4;            // output rows per block
static constexpr int SROWS = RPT + 2;    // staged rows incl. vertical halo

__device__ __forceinline__ float pt(float x, float n, float s, float w, float e) {
    // x*(ALPHA - 4*BETA) - ALPHA*x^3 + BETA*(n+s+w+e)
    const float c0 = ALPHA - 4.0f * BETA;
    float nb = (n + s) + (w + e);
    return fmaf(BETA, nb, fmaf(c0, x, -ALPHA * x * x * x));
}

__global__ __launch_bounds__(TPB, 8)
void allen_cahn_kernel(const float* __restrict__ in, float* __restrict__ out) {
    __shared__ float tile[SROWS][W];

    const int c4   = threadIdx.x;
    const int base = c4 * VEC;
    const int r0   = blockIdx.x * RPT;          // first output row of this block
    const int img  = blockIdx.y;

    const float* __restrict__ ip = in  + (size_t)img * H * W + base;
    float*       __restrict__ op = out + (size_t)img * H * W + base;

    // Front-batched, fully independent global loads (MLP_p1 = SROWS).
    float4 ld[SROWS];
#pragma unroll
    for (int j = 0; j < SROWS; j++) {
        int r = r0 + j - 1;
        r = (r < 0) ? 0 : ((r > H - 1) ? H - 1 : r);   // replication pad (vertical)
        ld[j] = *reinterpret_cast<const float4*>(ip + (size_t)r * W);
    }
#pragma unroll
    for (int j = 0; j < SROWS; j++)
        *reinterpret_cast<float4*>(&tile[j][base]) = ld[j];

    __syncthreads();

#pragma unroll
    for (int i = 0; i < RPT; i++) {
        const float4 up = *reinterpret_cast<const float4*>(&tile[i][base]);
        const float4 c  = *reinterpret_cast<const float4*>(&tile[i + 1][base]);
        const float4 dn = *reinterpret_cast<const float4*>(&tile[i + 2][base]);

        const float west = (base == 0)       ? c.x : tile[i + 1][base - 1];
        const float east = (base + VEC >= W) ? c.w : tile[i + 1][base + VEC];

        float4 o;
        o.x = pt(c.x, up.x, dn.x, west, c.y);
        o.y = pt(c.y, up.y, dn.y, c.x,  c.z);
        o.z = pt(c.z, up.z, dn.z, c.y,  c.w);
        o.w = pt(c.w, up.w, dn.w, c.z,  east);

        *reinterpret_cast<float4*>(op + (size_t)(r0 + i) * W) = o;
    }
}

extern "C" void kernel_launch(void* const* d_in, const int* in_sizes, int n_in,
                              void* d_out, int out_size) {
    const float* x0 = (const float*)d_in[0];
    float* out = (float*)d_out;
    dim3 grid(H / RPT, NIMG);
    allen_cahn_kernel<<<grid, TPB>>>(x0, out);
}

// round 4
// speedup vs baseline: 1.1831x; 1.1831x over previous
#include <cuda_runtime.h>

// Fused Allen-Cahn step:
//   out = ALPHA*x - ALPHA*x^3 + BETA*(N + S + W + E - 4x), replication pad.
// Shape: (16, 1, 1024, 1024) fp32. 64MB in + 64MB out.
// Strategy: 2 rows/block (4 front-batched independent row loads, no smem),
// streaming stores (__stcs) so the output never pollutes L2 -> input stays
// L2-resident across graph replays -> DRAM traffic ~= writes only.

#define ALPHA 400.0f
#define BETA  10000.0f

static constexpr int W = 1024;
static constexpr int H = 1024;
static constexpr int NIMG = 16;
static constexpr int VEC = 4;            // float4
static constexpr int TPB = W / VEC;      // 256 threads = one full row of float4
static constexpr int RPT = 2;            // output rows per block
static constexpr int LROWS = RPT + 2;    // rows loaded (incl. vertical halo)

__device__ __forceinline__ float pt(float x, float n, float s, float w, float e) {
    // x*(ALPHA - 4*BETA) - ALPHA*x^3 + BETA*(n+s+w+e)
    const float c0 = ALPHA - 4.0f * BETA;
    float nb = (n + s) + (w + e);
    return fmaf(BETA, nb, fmaf(c0, x, -ALPHA * x * x * x));
}

__global__ __launch_bounds__(TPB, 8)
void allen_cahn_kernel(const float* __restrict__ in, float* __restrict__ out) {
    const int c4   = threadIdx.x;
    const int base = c4 * VEC;
    const int r0   = blockIdx.x * RPT;       // first output row of this block
    const int img  = blockIdx.y;

    const float* __restrict__ ip = in  + (size_t)img * H * W + base;
    float*       __restrict__ op = out + (size_t)img * H * W + base;

    // Front-batched independent loads: rows r0-1 .. r0+RPT (clamped).
    float4 ld[LROWS];
#pragma unroll
    for (int j = 0; j < LROWS; j++) {
        int r = r0 + j - 1;
        r = (r < 0) ? 0 : ((r > H - 1) ? H - 1 : r);   // replication pad (vertical)
        ld[j] = *reinterpret_cast<const float4*>(ip + (size_t)r * W);
    }

#pragma unroll
    for (int i = 0; i < RPT; i++) {
        const int r = r0 + i;
        const float4 up = ld[i];
        const float4 c  = ld[i + 1];
        const float4 dn = ld[i + 2];

        // Horizontal halo: scalar loads (L1-hot; same lines as the float4 row).
        const float west = (base == 0)       ? c.x : ip[(size_t)r * W - 1];
        const float east = (base + VEC >= W) ? c.w : ip[(size_t)r * W + VEC];

        float4 o;
        o.x = pt(c.x, up.x, dn.x, west, c.y);
        o.y = pt(c.y, up.y, dn.y, c.x,  c.z);
        o.z = pt(c.z, up.z, dn.z, c.y,  c.w);
        o.w = pt(c.w, up.w, dn.w, c.z,  east);

        // Streaming store: evict-first, keep L2 for the input.
        __stcs(reinterpret_cast<float4*>(op + (size_t)r * W), o);
    }
}

extern "C" void kernel_launch(void* const* d_in, const int* in_sizes, int n_in,
                              void* d_out, int out_size) {
    const float* x0 = (const float*)d_in[0];
    float* out = (float*)d_out;
    dim3 grid(H / RPT, NIMG);
    allen_cahn_kernel<<<grid, TPB>>>(x0, out);
}

// round 6
// speedup vs baseline: 1.1847x; 1.0013x over previous
#include <cuda_runtime.h>

// Fused Allen-Cahn step:
//   out = ALPHA*x - ALPHA*x^3 + BETA*(N + S + W + E - 4x), replication pad.
// Shape: (16, 1, 1024, 1024) fp32. 64MB in + 64MB out.
// R6: 256-bit loads (ld.global.nc.L2::evict_last.v8.f32 — the only legal
//     evict_last ld form on sm_103a) + 256-bit streaming stores
//     (st.global.cs.v8.f32). Input stays L2-resident across graph replays;
//     DRAM traffic approaches the 64MB write floor. Halved LDG/STG count.

#define ALPHA 400.0f
#define BETA  10000.0f

static constexpr int W = 1024;
static constexpr int H = 1024;
static constexpr int NIMG = 16;
static constexpr int VEC = 8;            // float8 (256-bit)
static constexpr int TPB = W / VEC;      // 128 threads = one full row
static constexpr int RPT = 2;            // output rows per block
static constexpr int LROWS = RPT + 2;    // rows loaded (incl. vertical halo)

struct f8 { float v[8]; };

__device__ __forceinline__ f8 ldg_el_v8(const float* p) {
    f8 r;
    asm volatile("ld.global.nc.L2::evict_last.v8.f32 "
                 "{%0,%1,%2,%3,%4,%5,%6,%7}, [%8];"
                 : "=f"(r.v[0]), "=f"(r.v[1]), "=f"(r.v[2]), "=f"(r.v[3]),
                   "=f"(r.v[4]), "=f"(r.v[5]), "=f"(r.v[6]), "=f"(r.v[7])
                 : "l"(p));
    return r;
}

__device__ __forceinline__ void stg_cs_v8(float* p, const f8& r) {
    asm volatile("st.global.cs.v8.f32 [%8], {%0,%1,%2,%3,%4,%5,%6,%7};"
                 :: "f"(r.v[0]), "f"(r.v[1]), "f"(r.v[2]), "f"(r.v[3]),
                    "f"(r.v[4]), "f"(r.v[5]), "f"(r.v[6]), "f"(r.v[7]),
                    "l"(p)
                 : "memory");
}

__device__ __forceinline__ float pt(float x, float n, float s, float w, float e) {
    // x*(ALPHA - 4*BETA) - ALPHA*x^3 + BETA*(n+s+w+e)
    const float c0 = ALPHA - 4.0f * BETA;
    float nb = (n + s) + (w + e);
    return fmaf(BETA, nb, fmaf(c0, x, -ALPHA * x * x * x));
}

__global__ __launch_bounds__(TPB, 8)
void allen_cahn_kernel(const float* __restrict__ in, float* __restrict__ out) {
    const int tid  = threadIdx.x;
    const int base = tid * VEC;               // element column of v[0]
    const int r0   = blockIdx.x * RPT;        // first output row of this block
    const int img  = blockIdx.y;

    const float* __restrict__ ip = in  + (size_t)img * H * W + base;
    float*       __restrict__ op = out + (size_t)img * H * W + base;

    // Front-batched independent 256-bit loads: rows r0-1 .. r0+RPT (clamped).
    f8 ld[LROWS];
#pragma unroll
    for (int j = 0; j < LROWS; j++) {
        int r = r0 + j - 1;
        r = (r < 0) ? 0 : ((r > H - 1) ? H - 1 : r);   // replication pad (vertical)
        ld[j] = ldg_el_v8(ip + (size_t)r * W);
    }

#pragma unroll
    for (int i = 0; i < RPT; i++) {
        const int r = r0 + i;
        const f8& up = ld[i];
        const f8& c  = ld[i + 1];
        const f8& dn = ld[i + 2];

        // Horizontal halo: scalar loads (lines shared with neighbors' vectors).
        const float west = (base == 0)       ? c.v[0] : __ldg(ip + (size_t)r * W - 1);
        const float east = (base + VEC >= W) ? c.v[7] : __ldg(ip + (size_t)r * W + VEC);

        f8 o;
        o.v[0] = pt(c.v[0], up.v[0], dn.v[0], west,   c.v[1]);
#pragma unroll
        for (int k = 1; k < 7; k++)
            o.v[k] = pt(c.v[k], up.v[k], dn.v[k], c.v[k-1], c.v[k+1]);
        o.v[7] = pt(c.v[7], up.v[7], dn.v[7], c.v[6], east);

        stg_cs_v8(op + (size_t)r * W, o);
    }
}

extern "C" void kernel_launch(void* const* d_in, const int* in_sizes, int n_in,
                              void* d_out, int out_size) {
    const float* x0 = (const float*)d_in[0];
    float* out = (float*)d_out;
    dim3 grid(H / RPT, NIMG);
    allen_cahn_kernel<<<grid, TPB>>>(x0, out);
}

// round 7
// speedup vs baseline: 1.2653x; 1.0681x over previous
#include <cuda_runtime.h>

// Fused Allen-Cahn step:
//   out = ALPHA*x - ALPHA*x^3 + BETA*(N + S + W + E - 4x), replication pad.
// Shape: (16, 1, 1024, 1024) fp32. 64MB in + 64MB out. DRAM-traffic-bound.
// R7: v8 (256-bit) plain nc loads, v8 streaming stores, shuffle-based
//     horizontal halos (scalar LDG only at warp edges), occ ~69%.

#define ALPHA 400.0f
#define BETA  10000.0f

static constexpr int W = 1024;
static constexpr int H = 1024;
static constexpr int NIMG = 16;
static constexpr int VEC = 8;            // float8 (256-bit)
static constexpr int TPB = W / VEC;      // 128 threads = one full row
static constexpr int RPT = 2;            // output rows per block
static constexpr int LROWS = RPT + 2;    // rows loaded (incl. vertical halo)

struct f8 { float v[8]; };

__device__ __forceinline__ f8 ldg_v8(const float* p) {
    f8 r;
    asm volatile("ld.global.nc.v8.f32 {%0,%1,%2,%3,%4,%5,%6,%7}, [%8];"
                 : "=f"(r.v[0]), "=f"(r.v[1]), "=f"(r.v[2]), "=f"(r.v[3]),
                   "=f"(r.v[4]), "=f"(r.v[5]), "=f"(r.v[6]), "=f"(r.v[7])
                 : "l"(p));
    return r;
}

__device__ __forceinline__ void stg_cs_v8(float* p, const f8& r) {
    asm volatile("st.global.cs.v8.f32 [%8], {%0,%1,%2,%3,%4,%5,%6,%7};"
                 :: "f"(r.v[0]), "f"(r.v[1]), "f"(r.v[2]), "f"(r.v[3]),
                    "f"(r.v[4]), "f"(r.v[5]), "f"(r.v[6]), "f"(r.v[7]),
                    "l"(p)
                 : "memory");
}

__device__ __forceinline__ float pt(float x, float n, float s, float w, float e) {
    // x*(ALPHA - 4*BETA) - ALPHA*x^3 + BETA*(n+s+w+e)
    const float c0 = ALPHA - 4.0f * BETA;
    float nb = (n + s) + (w + e);
    return fmaf(BETA, nb, fmaf(c0, x, -ALPHA * x * x * x));
}

__global__ __launch_bounds__(TPB, 11)
void allen_cahn_kernel(const float* __restrict__ in, float* __restrict__ out) {
    const int tid  = threadIdx.x;
    const int base = tid * VEC;               // element column of v[0]
    const int r0   = blockIdx.x * RPT;        // first output row of this block
    const int img  = blockIdx.y;
    const int lane = tid & 31;
    const unsigned FULL = 0xFFFFFFFFu;

    const float* __restrict__ ip = in  + (size_t)img * H * W + base;
    float*       __restrict__ op = out + (size_t)img * H * W + base;

    // Front-batched independent 256-bit loads: rows r0-1 .. r0+RPT (clamped).
    f8 ld[LROWS];
#pragma unroll
    for (int j = 0; j < LROWS; j++) {
        int r = r0 + j - 1;
        r = (r < 0) ? 0 : ((r > H - 1) ? H - 1 : r);   // replication pad (vertical)
        ld[j] = ldg_v8(ip + (size_t)r * W);
    }

#pragma unroll
    for (int i = 0; i < RPT; i++) {
        const int r = r0 + i;
        const f8& up = ld[i];
        const f8& c  = ld[i + 1];
        const f8& dn = ld[i + 2];

        // Horizontal halo via warp shuffle; warp-edge lanes fall back to LDG.
        float west = __shfl_up_sync(FULL, c.v[7], 1);
        float east = __shfl_down_sync(FULL, c.v[0], 1);
        if (lane == 0)
            west = (base == 0)       ? c.v[0] : __ldg(ip + (size_t)r * W - 1);
        if (lane == 31)
            east = (base + VEC >= W) ? c.v[7] : __ldg(ip + (size_t)r * W + VEC);

        f8 o;
        o.v[0] = pt(c.v[0], up.v[0], dn.v[0], west, c.v[1]);
#pragma unroll
        for (int k = 1; k < 7; k++)
            o.v[k] = pt(c.v[k], up.v[k], dn.v[k], c.v[k-1], c.v[k+1]);
        o.v[7] = pt(c.v[7], up.v[7], dn.v[7], c.v[6], east);

        stg_cs_v8(op + (size_t)r * W, o);
    }
}

extern "C" void kernel_launch(void* const* d_in, const int* in_sizes, int n_in,
                              void* d_out, int out_size) {
    const float* x0 = (const float*)d_in[0];
    float* out = (float*)d_out;
    dim3 grid(H / RPT, NIMG);
    allen_cahn_kernel<<<grid, TPB>>>(x0, out);
}